// round 8
// baseline (speedup 1.0000x reference)
#include <cuda_runtime.h>
#include <cuda_fp16.h>
#include <cstddef>
#include <cstdint>

#define NN 50000
#define EE 800000
#define EPAD (EE + 3 * NN + 8)

// ---------------- scratch ----------------
__device__ __half g_h0[NN * 256];    // ping
__device__ __half g_h1[NN * 256];    // pong
__device__ int   g_deg[NN];
__device__ int   g_cursor[NN];
__device__ int   g_rowptr[NN + 1];
__device__ unsigned long long g_desc[256];
__device__ int    g_src[EPAD];
__device__ __half g_w[EPAD];         // w[p] = dinv[src[p]] (fp16)
__device__ float g_dinv[NN];

__device__ __forceinline__ __half2 u2h2(uint32_t u) {
    return *reinterpret_cast<__half2*>(&u);
}

// ---------------- CSR build + x->fp16 (fused) ----------------
__global__ void histconv_k(const int* __restrict__ col, int* deg, int e,
                           const float* __restrict__ x, __half2* __restrict__ x16,
                           int n4) {
    int i = blockIdx.x * blockDim.x + threadIdx.x;
    if (i < e) atomicAdd(&deg[col[i]], 1);
    if (i < n4) {
        float4 v = reinterpret_cast<const float4*>(x)[i];
        x16[2 * i]     = __floats2half2_rn(v.x, v.y);
        x16[2 * i + 1] = __floats2half2_rn(v.z, v.w);
    }
}

// fused: dinv + scan of padded degree (deg rounded up to 4) + dummy-slot zeroing
__global__ void scan_k(const int* __restrict__ deg, float* __restrict__ dinv,
                       int* __restrict__ rowptr, unsigned long long* desc,
                       int* __restrict__ src, __half* __restrict__ w, int n) {
    int b = blockIdx.x;
    int i = b * 256 + threadIdx.x;
    int lane = threadIdx.x & 31, wid = threadIdx.x >> 5;

    int d = (i < n) ? deg[i] : 0;
    int pv = (i < n) ? ((d + 3) & ~3) : 0;
    if (i < n) dinv[i] = rsqrtf((float)(d + 1));

    int x = pv;
    #pragma unroll
    for (int off = 1; off < 32; off <<= 1) {
        int t = __shfl_up_sync(0xFFFFFFFFu, x, off);
        if (lane >= off) x += t;
    }
    __shared__ int ws[8];
    __shared__ int s_prefix;
    if (lane == 31) ws[wid] = x;
    __syncthreads();
    if (wid == 0 && lane < 8) {
        int t2 = ws[lane];
        #pragma unroll
        for (int off = 1; off < 8; off <<= 1) {
            int t = __shfl_up_sync(0xFFu, t2, off);
            if (lane >= off) t2 += t;
        }
        ws[lane] = t2;
    }
    __syncthreads();
    int agg = ws[7];

    if (threadIdx.x == 0) {
        if (b == 0) {
            atomicExch(&desc[0], (2ull << 32) | (unsigned)agg);
            s_prefix = 0;
        } else {
            __threadfence();
            atomicExch(&desc[b], (1ull << 32) | (unsigned)agg);
            int prefix = 0;
            int j = b - 1;
            while (true) {
                unsigned long long dj;
                do { dj = atomicAdd(&desc[j], 0ull); } while ((dj >> 32) == 0);
                prefix += (int)(unsigned)dj;
                if ((dj >> 32) == 2) break;
                j--;
            }
            __threadfence();
            atomicExch(&desc[b], (2ull << 32) | (unsigned)(prefix + agg));
            s_prefix = prefix;
        }
    }
    __syncthreads();
    int excl = s_prefix + (wid ? ws[wid - 1] : 0) + (x - pv);
    if (i < n) {
        rowptr[i] = excl;
        if (i == n - 1) rowptr[n] = excl + pv;
        // zero dummy slots
        for (int j = d; j < pv; j++) {
            src[excl + j] = 0;
            w[excl + j] = __float2half_rn(0.0f);
        }
    }
}

__global__ void fill_k(const int* __restrict__ row, const int* __restrict__ col,
                       const int* __restrict__ rowptr, int* cursor,
                       int* src, __half* w, const float* __restrict__ dinv, int e) {
    int i = blockIdx.x * blockDim.x + threadIdx.x;
    if (i < e) {
        int r = row[i], c = col[i];
        int p = rowptr[c] + atomicAdd(&cursor[c], 1);
        src[p] = r;
        w[p] = __float2half_rn(dinv[r]);
    }
}

// ---------------- aggregation (fp16 in/out), warp per node, chunked HFMA2 ----------------
// out[v] = act( dinv[v] * ( dinv[v]*h[v] + sum_e w[e]*h[src[e]] ) + bias )
// edge segments padded to multiples of 4; dummy edges have w=0.
template <int VEC, bool BIAS, bool RELU>
__global__ void agg_h(const __half* __restrict__ h, __half* __restrict__ out,
                      const int* __restrict__ rowptr, const int* __restrict__ src,
                      const __half* __restrict__ w, const float* __restrict__ dinv,
                      const float* __restrict__ bias, int nNodes) {
    constexpr int F = 32 * VEC;
    int gw = (blockIdx.x * blockDim.x + threadIdx.x) >> 5;
    int lane = threadIdx.x & 31;
    if (gw >= nNodes) return;
    int v = gw;
    int foff = lane * VEC;

    float acc[VEC];
    float dv = dinv[v];

    {
        const __half* hp = h + (size_t)v * F + foff;
        if constexpr (VEC == 4) {
            uint2 r = *reinterpret_cast<const uint2*>(hp);
            float2 f0 = __half22float2(u2h2(r.x));
            float2 f1 = __half22float2(u2h2(r.y));
            acc[0] = dv * f0.x; acc[1] = dv * f0.y; acc[2] = dv * f1.x; acc[3] = dv * f1.y;
        } else if constexpr (VEC == 2) {
            float2 f = __half22float2(*reinterpret_cast<const __half2*>(hp));
            acc[0] = dv * f.x; acc[1] = dv * f.y;
        } else {
            acc[0] = dv * __half2float(*hp);
        }
    }

    int e0 = rowptr[v], e1 = rowptr[v + 1];
    for (int e = e0; e < e1; e += 4) {
        int4 s4 = *reinterpret_cast<const int4*>(src + e);
        uint2 w4 = *reinterpret_cast<const uint2*>(w + e);
        __half2 wl = u2h2(w4.x), wh = u2h2(w4.y);
        __half2 w0 = __low2half2(wl), w1 = __high2half2(wl);
        __half2 w2 = __low2half2(wh), w3 = __high2half2(wh);

        if constexpr (VEC == 4) {
            uint2 d0 = *reinterpret_cast<const uint2*>(h + (size_t)s4.x * F + foff);
            uint2 d1 = *reinterpret_cast<const uint2*>(h + (size_t)s4.y * F + foff);
            uint2 d2 = *reinterpret_cast<const uint2*>(h + (size_t)s4.z * F + foff);
            uint2 d3 = *reinterpret_cast<const uint2*>(h + (size_t)s4.w * F + foff);
            __half2 z = __float2half2_rn(0.0f);
            __half2 p0 = z, p1 = z;
            p0 = __hfma2(w0, u2h2(d0.x), p0); p1 = __hfma2(w0, u2h2(d0.y), p1);
            p0 = __hfma2(w1, u2h2(d1.x), p0); p1 = __hfma2(w1, u2h2(d1.y), p1);
            p0 = __hfma2(w2, u2h2(d2.x), p0); p1 = __hfma2(w2, u2h2(d2.y), p1);
            p0 = __hfma2(w3, u2h2(d3.x), p0); p1 = __hfma2(w3, u2h2(d3.y), p1);
            float2 f0 = __half22float2(p0), f1 = __half22float2(p1);
            acc[0] += f0.x; acc[1] += f0.y; acc[2] += f1.x; acc[3] += f1.y;
        } else if constexpr (VEC == 2) {
            __half2 d0 = *reinterpret_cast<const __half2*>(h + (size_t)s4.x * F + foff);
            __half2 d1 = *reinterpret_cast<const __half2*>(h + (size_t)s4.y * F + foff);
            __half2 d2 = *reinterpret_cast<const __half2*>(h + (size_t)s4.z * F + foff);
            __half2 d3 = *reinterpret_cast<const __half2*>(h + (size_t)s4.w * F + foff);
            __half2 p = __float2half2_rn(0.0f);
            p = __hfma2(w0, d0, p);
            p = __hfma2(w1, d1, p);
            p = __hfma2(w2, d2, p);
            p = __hfma2(w3, d3, p);
            float2 f = __half22float2(p);
            acc[0] += f.x; acc[1] += f.y;
        } else {
            __half d0 = h[(size_t)s4.x * F + foff];
            __half d1 = h[(size_t)s4.y * F + foff];
            __half d2 = h[(size_t)s4.z * F + foff];
            __half d3 = h[(size_t)s4.w * F + foff];
            __half p = __float2half_rn(0.0f);
            p = __hfma(__low2half(wl), d0, p);
            p = __hfma(__high2half(wl), d1, p);
            p = __hfma(__low2half(wh), d2, p);
            p = __hfma(__high2half(wh), d3, p);
            acc[0] += __half2float(p);
        }
    }

    #pragma unroll
    for (int i = 0; i < VEC; i++) {
        float r = dv * acc[i];
        if (BIAS) r += bias[foff + i];
        if (RELU) r = fmaxf(r, 0.0f);
        acc[i] = r;
    }

    __half* op = out + (size_t)v * F + foff;
    if constexpr (VEC == 4) {
        uint2 o;
        *reinterpret_cast<__half2*>(&o.x) = __floats2half2_rn(acc[0], acc[1]);
        *reinterpret_cast<__half2*>(&o.y) = __floats2half2_rn(acc[2], acc[3]);
        *reinterpret_cast<uint2*>(op) = o;
    } else if constexpr (VEC == 2) {
        *reinterpret_cast<__half2*>(op) = __floats2half2_rn(acc[0], acc[1]);
    } else {
        op[0] = __float2half_rn(acc[0]);
    }
}

// ---------------- fp16 tensor-core GEMM (m16n8k16, 256 threads, 8 warps) ----------------
template <int AN, bool BIAS, bool RELU, bool OUTH>
__global__ __launch_bounds__(256, 2)
void gemm_h(const __half* __restrict__ A, const float* __restrict__ B,
            const float* __restrict__ bias, void* __restrict__ Cp,
            int M, int K, int Nc) {
    constexpr int BN = 2 * AN * 8;
    __shared__ uint32_t As[2][4][132][2];
    __shared__ uint32_t Bs[2][4][2][BN + 4];

    const int tid = threadIdx.x;
    const int lane = tid & 31, wid = tid >> 5;
    const int g = lane >> 2, tg = lane & 3;
    const int wm = wid & 3, wn = wid >> 2;

    const int bm = blockIdx.y * 128;
    const int bn = blockIdx.x * BN;

    float acc[2][AN][4];
    #pragma unroll
    for (int i = 0; i < 2; i++)
        #pragma unroll
        for (int j = 0; j < AN; j++)
            #pragma unroll
            for (int c = 0; c < 4; c++) acc[i][j][c] = 0.0f;

    const int arow_l = tid >> 1;
    const int kh = (tid & 1) * 16;
    const int akk = kh >> 4;
    const int arow = min(bm + arow_l, M - 1);
    const __half* Abase = A + (size_t)arow * K + kh;

    const int kp = tid >> 4;
    const int kloc = kp * 2;
    const int bkk = kloc >> 4, bp = (kloc >> 3) & 1, bc = (kloc >> 1) & 3;
    const int nseg = tid & 15;

    for (int kt = 0; kt < K; kt += 32) {
        __syncthreads();
        {
            uint4 v0 = *reinterpret_cast<const uint4*>(Abase + kt);
            uint4 v1 = *reinterpret_cast<const uint4*>(Abase + kt + 8);
            As[akk][0][arow_l][0] = v0.x;
            As[akk][1][arow_l][0] = v0.y;
            As[akk][2][arow_l][0] = v0.z;
            As[akk][3][arow_l][0] = v0.w;
            As[akk][0][arow_l][1] = v1.x;
            As[akk][1][arow_l][1] = v1.y;
            As[akk][2][arow_l][1] = v1.z;
            As[akk][3][arow_l][1] = v1.w;
        }
        {
            const float* r0 = B + (size_t)(kt + kloc) * Nc + bn;
            const float* r1 = r0 + Nc;
            #pragma unroll
            for (int j = 0; j < BN / 16; j++) {
                int n = nseg + 16 * j;
                __half2 pk = __floats2half2_rn(r0[n], r1[n]);
                Bs[bkk][bc][bp][n] = *reinterpret_cast<uint32_t*>(&pk);
            }
        }
        __syncthreads();

        #pragma unroll
        for (int kk = 0; kk < 2; kk++) {
            uint32_t a[2][4];
            #pragma unroll
            for (int ma = 0; ma < 2; ma++) {
                int mb = wm * 32 + ma * 16;
                uint2 lo = *reinterpret_cast<const uint2*>(&As[kk][tg][mb + g][0]);
                uint2 hi = *reinterpret_cast<const uint2*>(&As[kk][tg][mb + 8 + g][0]);
                a[ma][0] = lo.x; a[ma][2] = lo.y;
                a[ma][1] = hi.x; a[ma][3] = hi.y;
            }
            uint32_t b[AN][2];
            #pragma unroll
            for (int na = 0; na < AN; na++) {
                int n = wn * AN * 8 + na * 8 + g;
                b[na][0] = Bs[kk][tg][0][n];
                b[na][1] = Bs[kk][tg][1][n];
            }
            #pragma unroll
            for (int ma = 0; ma < 2; ma++)
                #pragma unroll
                for (int na = 0; na < AN; na++) {
                    asm volatile(
                        "mma.sync.aligned.m16n8k16.row.col.f32.f16.f16.f32 "
                        "{%0,%1,%2,%3}, {%4,%5,%6,%7}, {%8,%9}, {%0,%1,%2,%3};\n"
                        : "+f"(acc[ma][na][0]), "+f"(acc[ma][na][1]),
                          "+f"(acc[ma][na][2]), "+f"(acc[ma][na][3])
                        : "r"(a[ma][0]), "r"(a[ma][1]), "r"(a[ma][2]), "r"(a[ma][3]),
                          "r"(b[na][0]), "r"(b[na][1]));
                }
        }
    }

    #pragma unroll
    for (int ma = 0; ma < 2; ma++) {
        int m0 = bm + wm * 32 + ma * 16 + g;
        #pragma unroll
        for (int na = 0; na < AN; na++) {
            int n = bn + wn * AN * 8 + na * 8 + 2 * tg;
            float bx = 0.f, by = 0.f;
            if (BIAS) { bx = bias[n]; by = bias[n + 1]; }
            float v0 = acc[ma][na][0] + bx, v1 = acc[ma][na][1] + by;
            float v2 = acc[ma][na][2] + bx, v3 = acc[ma][na][3] + by;
            if (RELU) {
                v0 = fmaxf(v0, 0.f); v1 = fmaxf(v1, 0.f);
                v2 = fmaxf(v2, 0.f); v3 = fmaxf(v3, 0.f);
            }
            if constexpr (OUTH) {
                __half* C = (__half*)Cp;
                if (m0 < M)
                    *reinterpret_cast<__half2*>(C + (size_t)m0 * Nc + n) = __floats2half2_rn(v0, v1);
                if (m0 + 8 < M)
                    *reinterpret_cast<__half2*>(C + (size_t)(m0 + 8) * Nc + n) = __floats2half2_rn(v2, v3);
            } else {
                float* C = (float*)Cp;
                if (m0 < M) {
                    float2 o; o.x = v0; o.y = v1;
                    *reinterpret_cast<float2*>(C + (size_t)m0 * Nc + n) = o;
                }
                if (m0 + 8 < M) {
                    float2 o; o.x = v2; o.y = v3;
                    *reinterpret_cast<float2*>(C + (size_t)(m0 + 8) * Nc + n) = o;
                }
            }
        }
    }
}

// ---------------- fused heads: z = agg(h4); mu = zWmu+bmu; ls = zWls+bls ----------------
// warp per node; lanes 0-15 compute mu columns, lanes 16-31 ls columns.
__global__ __launch_bounds__(256)
void heads_f(const __half* __restrict__ h4,
             const int* __restrict__ rowptr, const int* __restrict__ src,
             const __half* __restrict__ w, const float* __restrict__ dinv,
             const float* __restrict__ Wmu, const float* __restrict__ bmu,
             const float* __restrict__ Wls, const float* __restrict__ bls,
             float* __restrict__ out_mu, float* __restrict__ out_ls, int n) {
    __shared__ float sW[2][32][17];
    __shared__ float sz[8][32];
    int tid = threadIdx.x;
    for (int t = tid; t < 512; t += 256) {
        sW[0][t >> 4][t & 15] = Wmu[t];
        sW[1][t >> 4][t & 15] = Wls[t];
    }
    __syncthreads();

    int wid = tid >> 5, lane = tid & 31;
    int v = blockIdx.x * 8 + wid;
    if (v < n) {
        float dv = dinv[v];
        float acc = dv * __half2float(h4[(size_t)v * 32 + lane]);
        int e0 = rowptr[v], e1 = rowptr[v + 1];
        for (int e = e0; e < e1; e += 4) {
            int4 s4 = *reinterpret_cast<const int4*>(src + e);
            uint2 w4 = *reinterpret_cast<const uint2*>(w + e);
            __half2 wl = u2h2(w4.x), wh = u2h2(w4.y);
            __half d0 = h4[(size_t)s4.x * 32 + lane];
            __half d1 = h4[(size_t)s4.y * 32 + lane];
            __half d2 = h4[(size_t)s4.z * 32 + lane];
            __half d3 = h4[(size_t)s4.w * 32 + lane];
            __half p = __float2half_rn(0.0f);
            p = __hfma(__low2half(wl), d0, p);
            p = __hfma(__high2half(wl), d1, p);
            p = __hfma(__low2half(wh), d2, p);
            p = __hfma(__high2half(wh), d3, p);
            acc += __half2float(p);
        }
        sz[wid][lane] = dv * acc;
    }
    __syncwarp();
    if (v < n) {
        int which = lane >> 4;
        int i = lane & 15;
        float a = which ? bls[i] : bmu[i];
        #pragma unroll
        for (int k = 0; k < 32; k++) a += sz[wid][k] * sW[which][k][i];
        float* outp = which ? out_ls : out_mu;
        outp[(size_t)v * 16 + i] = a;
    }
}

// ---------------- host ----------------
static inline void* sym(const void* s) {
    void* p = nullptr;
    cudaGetSymbolAddress(&p, s);
    return p;
}

extern "C" void kernel_launch(void* const* d_in, const int* in_sizes, int n_in,
                              void* d_out, int out_size) {
    const float* x   = (const float*)d_in[0];
    const int*   ei  = (const int*)d_in[1];
    const float* W1  = (const float*)d_in[2];
    const float* b1  = (const float*)d_in[3];
    const float* W2  = (const float*)d_in[4];
    const float* b2  = (const float*)d_in[5];
    const float* W3  = (const float*)d_in[6];
    const float* b3  = (const float*)d_in[7];
    const float* W4  = (const float*)d_in[8];
    const float* b4  = (const float*)d_in[9];
    const float* Wmu = (const float*)d_in[10];
    const float* bmu = (const float*)d_in[11];
    const float* Wls = (const float*)d_in[12];
    const float* bls = (const float*)d_in[13];

    const int N = NN;
    const int E = in_sizes[1] / 2;
    const int* row = ei;
    const int* col = ei + E;

    __half* h0 = (__half*)sym(g_h0);
    __half* h1 = (__half*)sym(g_h1);
    int*   deg  = (int*)sym(g_deg);
    int*   cur  = (int*)sym(g_cursor);
    int*   rp   = (int*)sym(g_rowptr);
    unsigned long long* desc = (unsigned long long*)sym(g_desc);
    int*    srcA = (int*)sym(g_src);
    __half* wA   = (__half*)sym(g_w);
    float* dinv = (float*)sym(g_dinv);

    float* out_mu = (float*)d_out;
    float* out_ls = out_mu + (size_t)N * 16;

    const int NB = (N + 255) / 256;
    const int n4 = N * 128 / 4;

    // ---- CSR build + x->fp16 ----
    cudaMemsetAsync(deg, 0, NN * sizeof(int));
    cudaMemsetAsync(cur, 0, NN * sizeof(int));
    cudaMemsetAsync(desc, 0, 256 * sizeof(unsigned long long));
    histconv_k<<<(n4 + 255) / 256, 256>>>(col, deg, E, x, (__half2*)h0, n4);   // x16 -> h0
    scan_k<<<NB, 256>>>(deg, dinv, rp, desc, srcA, wA, N);
    fill_k<<<(E + 255) / 256, 256>>>(row, col, rp, cur, srcA, wA, dinv, E);

    const int AGG_BLOCKS = (N + 7) / 8;
    const int GY = (N + 127) / 128;

    // L1: agg(x16:h0) -> a1:h1 ; gemm(a1, W1) +b1+relu -> h1g:h0 [N,256]
    agg_h<4, false, false><<<AGG_BLOCKS, 256>>>(h0, h1, rp, srcA, wA, dinv, nullptr, N);
    { dim3 g(2, GY); gemm_h<8, true, true, true><<<g, 256>>>(h1, W1, b1, h0, N, 128, 256); }
    // L2: gemm(h1g, W2) -> t2:h1 [N,128] ; agg +b2+relu -> a2:h0
    { dim3 g(1, GY); gemm_h<8, false, false, true><<<g, 256>>>(h0, W2, nullptr, h1, N, 256, 128); }
    agg_h<4, true, true><<<AGG_BLOCKS, 256>>>(h1, h0, rp, srcA, wA, dinv, b2, N);
    // L3: gemm(a2, W3) -> t3:h1 [N,64] ; agg +b3+relu -> a3:h0
    { dim3 g(1, GY); gemm_h<4, false, false, true><<<g, 256>>>(h0, W3, nullptr, h1, N, 128, 64); }
    agg_h<2, true, true><<<AGG_BLOCKS, 256>>>(h1, h0, rp, srcA, wA, dinv, b3, N);
    // L4: gemm(a3, W4) -> t4:h1 [N,32] ; agg +b4+relu -> h4:h0
    { dim3 g(1, GY); gemm_h<2, false, false, true><<<g, 256>>>(h0, W4, nullptr, h1, N, 64, 32); }
    agg_h<1, true, true><<<AGG_BLOCKS, 256>>>(h1, h0, rp, srcA, wA, dinv, b4, N);
    // fused heads: z = agg(h4:h0), mu/ls GEMM
    heads_f<<<AGG_BLOCKS, 256>>>(h0, rp, srcA, wA, dinv, Wmu, bmu, Wls, bls,
                                 out_mu, out_ls, N);
}

// round 9
// speedup vs baseline: 1.0140x; 1.0140x over previous
#include <cuda_runtime.h>
#include <cuda_fp16.h>
#include <cstddef>
#include <cstdint>

#define NN 50000
#define EE 800000
#define EPAD (EE + 3 * NN + 8)

// ---------------- scratch ----------------
__device__ __half g_h0[NN * 256];    // ping
__device__ __half g_h1[NN * 256];    // pong
__device__ int   g_deg[NN];
__device__ int   g_cursor[NN];
__device__ int   g_rowptr[NN + 1];
__device__ unsigned long long g_desc[256];
__device__ int    g_src[EPAD];
__device__ __half g_w[EPAD];         // w[p] = dinv[src[p]] (fp16)
__device__ float g_dinv[NN];

__device__ __forceinline__ __half2 u2h2(uint32_t u) {
    return *reinterpret_cast<__half2*>(&u);
}

// ---------------- CSR build + x->fp16 (fused) ----------------
__global__ void histconv_k(const int* __restrict__ col, int* deg, int e,
                           const float* __restrict__ x, __half2* __restrict__ x16,
                           int n4) {
    int i = blockIdx.x * blockDim.x + threadIdx.x;
    if (i < e) atomicAdd(&deg[col[i]], 1);
    if (i < n4) {
        float4 v = reinterpret_cast<const float4*>(x)[i];
        x16[2 * i]     = __floats2half2_rn(v.x, v.y);
        x16[2 * i + 1] = __floats2half2_rn(v.z, v.w);
    }
}

// fused: dinv + scan of padded degree (deg rounded up to 4) + dummy-slot zeroing
__global__ void scan_k(const int* __restrict__ deg, float* __restrict__ dinv,
                       int* __restrict__ rowptr, unsigned long long* desc,
                       int* __restrict__ src, __half* __restrict__ w, int n) {
    int b = blockIdx.x;
    int i = b * 256 + threadIdx.x;
    int lane = threadIdx.x & 31, wid = threadIdx.x >> 5;

    int d = (i < n) ? deg[i] : 0;
    int pv = (i < n) ? ((d + 3) & ~3) : 0;
    if (i < n) dinv[i] = rsqrtf((float)(d + 1));

    int x = pv;
    #pragma unroll
    for (int off = 1; off < 32; off <<= 1) {
        int t = __shfl_up_sync(0xFFFFFFFFu, x, off);
        if (lane >= off) x += t;
    }
    __shared__ int ws[8];
    __shared__ int s_prefix;
    if (lane == 31) ws[wid] = x;
    __syncthreads();
    if (wid == 0 && lane < 8) {
        int t2 = ws[lane];
        #pragma unroll
        for (int off = 1; off < 8; off <<= 1) {
            int t = __shfl_up_sync(0xFFu, t2, off);
            if (lane >= off) t2 += t;
        }
        ws[lane] = t2;
    }
    __syncthreads();
    int agg = ws[7];

    if (threadIdx.x == 0) {
        if (b == 0) {
            atomicExch(&desc[0], (2ull << 32) | (unsigned)agg);
            s_prefix = 0;
        } else {
            __threadfence();
            atomicExch(&desc[b], (1ull << 32) | (unsigned)agg);
            int prefix = 0;
            int j = b - 1;
            while (true) {
                unsigned long long dj;
                do { dj = atomicAdd(&desc[j], 0ull); } while ((dj >> 32) == 0);
                prefix += (int)(unsigned)dj;
                if ((dj >> 32) == 2) break;
                j--;
            }
            __threadfence();
            atomicExch(&desc[b], (2ull << 32) | (unsigned)(prefix + agg));
            s_prefix = prefix;
        }
    }
    __syncthreads();
    int excl = s_prefix + (wid ? ws[wid - 1] : 0) + (x - pv);
    if (i < n) {
        rowptr[i] = excl;
        if (i == n - 1) rowptr[n] = excl + pv;
        for (int j = d; j < pv; j++) {
            src[excl + j] = 0;
            w[excl + j] = __float2half_rn(0.0f);
        }
    }
}

__global__ void fill_k(const int* __restrict__ row, const int* __restrict__ col,
                       const int* __restrict__ rowptr, int* cursor,
                       int* src, __half* w, const float* __restrict__ dinv, int e) {
    int i = blockIdx.x * blockDim.x + threadIdx.x;
    if (i < e) {
        int r = row[i], c = col[i];
        int p = rowptr[c] + atomicAdd(&cursor[c], 1);
        src[p] = r;
        w[p] = __float2half_rn(dinv[r]);
    }
}

// ---------------- aggregation (fp16 in/out), warp per node ----------------
// padded CSR (segments multiple of 4, dummy w=0); fp32 FFMA accumulation.
template <int VEC, bool BIAS, bool RELU>
__global__ void agg_h(const __half* __restrict__ h, __half* __restrict__ out,
                      const int* __restrict__ rowptr, const int* __restrict__ src,
                      const __half* __restrict__ w, const float* __restrict__ dinv,
                      const float* __restrict__ bias, int nNodes) {
    constexpr int F = 32 * VEC;
    int gw = (blockIdx.x * blockDim.x + threadIdx.x) >> 5;
    int lane = threadIdx.x & 31;
    if (gw >= nNodes) return;
    int v = gw;
    int foff = lane * VEC;

    float acc[VEC];
    float dv = dinv[v];

    {
        const __half* hp = h + (size_t)v * F + foff;
        if constexpr (VEC == 4) {
            uint2 r = *reinterpret_cast<const uint2*>(hp);
            float2 f0 = __half22float2(u2h2(r.x));
            float2 f1 = __half22float2(u2h2(r.y));
            acc[0] = dv * f0.x; acc[1] = dv * f0.y; acc[2] = dv * f1.x; acc[3] = dv * f1.y;
        } else if constexpr (VEC == 2) {
            float2 f = __half22float2(*reinterpret_cast<const __half2*>(hp));
            acc[0] = dv * f.x; acc[1] = dv * f.y;
        } else {
            acc[0] = dv * __half2float(*hp);
        }
    }

    int e0 = rowptr[v], e1 = rowptr[v + 1];
    for (int e = e0; e < e1; e += 4) {
        int4 s4 = *reinterpret_cast<const int4*>(src + e);
        uint2 w4 = *reinterpret_cast<const uint2*>(w + e);
        float2 wlo = __half22float2(u2h2(w4.x));   // w0, w1
        float2 whi = __half22float2(u2h2(w4.y));   // w2, w3

        if constexpr (VEC == 4) {
            uint2 d0 = *reinterpret_cast<const uint2*>(h + (size_t)s4.x * F + foff);
            uint2 d1 = *reinterpret_cast<const uint2*>(h + (size_t)s4.y * F + foff);
            uint2 d2 = *reinterpret_cast<const uint2*>(h + (size_t)s4.z * F + foff);
            uint2 d3 = *reinterpret_cast<const uint2*>(h + (size_t)s4.w * F + foff);
            float2 a0 = __half22float2(u2h2(d0.x)), b0 = __half22float2(u2h2(d0.y));
            float2 a1 = __half22float2(u2h2(d1.x)), b1 = __half22float2(u2h2(d1.y));
            float2 a2 = __half22float2(u2h2(d2.x)), b2 = __half22float2(u2h2(d2.y));
            float2 a3 = __half22float2(u2h2(d3.x)), b3 = __half22float2(u2h2(d3.y));
            acc[0] += wlo.x * a0.x; acc[1] += wlo.x * a0.y; acc[2] += wlo.x * b0.x; acc[3] += wlo.x * b0.y;
            acc[0] += wlo.y * a1.x; acc[1] += wlo.y * a1.y; acc[2] += wlo.y * b1.x; acc[3] += wlo.y * b1.y;
            acc[0] += whi.x * a2.x; acc[1] += whi.x * a2.y; acc[2] += whi.x * b2.x; acc[3] += whi.x * b2.y;
            acc[0] += whi.y * a3.x; acc[1] += whi.y * a3.y; acc[2] += whi.y * b3.x; acc[3] += whi.y * b3.y;
        } else if constexpr (VEC == 2) {
            float2 f0 = __half22float2(*reinterpret_cast<const __half2*>(h + (size_t)s4.x * F + foff));
            float2 f1 = __half22float2(*reinterpret_cast<const __half2*>(h + (size_t)s4.y * F + foff));
            float2 f2 = __half22float2(*reinterpret_cast<const __half2*>(h + (size_t)s4.z * F + foff));
            float2 f3 = __half22float2(*reinterpret_cast<const __half2*>(h + (size_t)s4.w * F + foff));
            acc[0] += wlo.x * f0.x; acc[1] += wlo.x * f0.y;
            acc[0] += wlo.y * f1.x; acc[1] += wlo.y * f1.y;
            acc[0] += whi.x * f2.x; acc[1] += whi.x * f2.y;
            acc[0] += whi.y * f3.x; acc[1] += whi.y * f3.y;
        } else {
            float t0 = __half2float(h[(size_t)s4.x * F + foff]);
            float t1 = __half2float(h[(size_t)s4.y * F + foff]);
            float t2 = __half2float(h[(size_t)s4.z * F + foff]);
            float t3 = __half2float(h[(size_t)s4.w * F + foff]);
            acc[0] += wlo.x * t0 + wlo.y * t1 + whi.x * t2 + whi.y * t3;
        }
    }

    #pragma unroll
    for (int i = 0; i < VEC; i++) {
        float r = dv * acc[i];
        if (BIAS) r += bias[foff + i];
        if (RELU) r = fmaxf(r, 0.0f);
        acc[i] = r;
    }

    __half* op = out + (size_t)v * F + foff;
    if constexpr (VEC == 4) {
        uint2 o;
        *reinterpret_cast<__half2*>(&o.x) = __floats2half2_rn(acc[0], acc[1]);
        *reinterpret_cast<__half2*>(&o.y) = __floats2half2_rn(acc[2], acc[3]);
        *reinterpret_cast<uint2*>(op) = o;
    } else if constexpr (VEC == 2) {
        *reinterpret_cast<__half2*>(op) = __floats2half2_rn(acc[0], acc[1]);
    } else {
        op[0] = __float2half_rn(acc[0]);
    }
}

// ---------------- fp16 tensor-core GEMM (m16n8k16, 256 threads, 8 warps) ----------------
// register-prefetch software pipeline: store staged regs -> sync -> load next -> mma -> sync
template <int AN, bool BIAS, bool RELU, bool OUTH>
__global__ __launch_bounds__(256, 2)
void gemm_h(const __half* __restrict__ A, const float* __restrict__ B,
            const float* __restrict__ bias, void* __restrict__ Cp,
            int M, int K, int Nc) {
    constexpr int BN = 2 * AN * 8;
    constexpr int NJ = BN / 16;
    __shared__ uint32_t As[2][4][132][2];
    __shared__ uint32_t Bs[2][4][2][BN + 4];

    const int tid = threadIdx.x;
    const int lane = tid & 31, wid = tid >> 5;
    const int g = lane >> 2, tg = lane & 3;
    const int wm = wid & 3, wn = wid >> 2;

    const int bm = blockIdx.y * 128;
    const int bn = blockIdx.x * BN;

    float acc[2][AN][4];
    #pragma unroll
    for (int i = 0; i < 2; i++)
        #pragma unroll
        for (int j = 0; j < AN; j++)
            #pragma unroll
            for (int c = 0; c < 4; c++) acc[i][j][c] = 0.0f;

    const int arow_l = tid >> 1;
    const int kh = (tid & 1) * 16;
    const int akk = kh >> 4;
    const int arow = min(bm + arow_l, M - 1);
    const __half* Abase = A + (size_t)arow * K + kh;

    const int kp = tid >> 4;
    const int kloc = kp * 2;
    const int bkk = kloc >> 4, bp = (kloc >> 3) & 1, bc = (kloc >> 1) & 3;
    const int nseg = tid & 15;

    // stage registers
    uint4 sa0, sa1;
    float sb0[NJ], sb1[NJ];
    {
        sa0 = *reinterpret_cast<const uint4*>(Abase);
        sa1 = *reinterpret_cast<const uint4*>(Abase + 8);
        const float* r0 = B + (size_t)kloc * Nc + bn;
        const float* r1 = r0 + Nc;
        #pragma unroll
        for (int j = 0; j < NJ; j++) {
            int n = nseg + 16 * j;
            sb0[j] = r0[n];
            sb1[j] = r1[n];
        }
    }

    for (int kt = 0; kt < K; kt += 32) {
        // ---- store staged regs to smem ----
        As[akk][0][arow_l][0] = sa0.x;
        As[akk][1][arow_l][0] = sa0.y;
        As[akk][2][arow_l][0] = sa0.z;
        As[akk][3][arow_l][0] = sa0.w;
        As[akk][0][arow_l][1] = sa1.x;
        As[akk][1][arow_l][1] = sa1.y;
        As[akk][2][arow_l][1] = sa1.z;
        As[akk][3][arow_l][1] = sa1.w;
        #pragma unroll
        for (int j = 0; j < NJ; j++) {
            int n = nseg + 16 * j;
            __half2 pk = __floats2half2_rn(sb0[j], sb1[j]);
            Bs[bkk][bc][bp][n] = *reinterpret_cast<uint32_t*>(&pk);
        }
        __syncthreads();

        // ---- issue next-tile loads (overlap with mma) ----
        if (kt + 32 < K) {
            sa0 = *reinterpret_cast<const uint4*>(Abase + kt + 32);
            sa1 = *reinterpret_cast<const uint4*>(Abase + kt + 40);
            const float* r0 = B + (size_t)(kt + 32 + kloc) * Nc + bn;
            const float* r1 = r0 + Nc;
            #pragma unroll
            for (int j = 0; j < NJ; j++) {
                int n = nseg + 16 * j;
                sb0[j] = r0[n];
                sb1[j] = r1[n];
            }
        }

        // ---- 2 k16 mma steps ----
        #pragma unroll
        for (int kk = 0; kk < 2; kk++) {
            uint32_t a[2][4];
            #pragma unroll
            for (int ma = 0; ma < 2; ma++) {
                int mb = wm * 32 + ma * 16;
                uint2 lo = *reinterpret_cast<const uint2*>(&As[kk][tg][mb + g][0]);
                uint2 hi = *reinterpret_cast<const uint2*>(&As[kk][tg][mb + 8 + g][0]);
                a[ma][0] = lo.x; a[ma][2] = lo.y;
                a[ma][1] = hi.x; a[ma][3] = hi.y;
            }
            uint32_t b[AN][2];
            #pragma unroll
            for (int na = 0; na < AN; na++) {
                int n = wn * AN * 8 + na * 8 + g;
                b[na][0] = Bs[kk][tg][0][n];
                b[na][1] = Bs[kk][tg][1][n];
            }
            #pragma unroll
            for (int ma = 0; ma < 2; ma++)
                #pragma unroll
                for (int na = 0; na < AN; na++) {
                    asm volatile(
                        "mma.sync.aligned.m16n8k16.row.col.f32.f16.f16.f32 "
                        "{%0,%1,%2,%3}, {%4,%5,%6,%7}, {%8,%9}, {%0,%1,%2,%3};\n"
                        : "+f"(acc[ma][na][0]), "+f"(acc[ma][na][1]),
                          "+f"(acc[ma][na][2]), "+f"(acc[ma][na][3])
                        : "r"(a[ma][0]), "r"(a[ma][1]), "r"(a[ma][2]), "r"(a[ma][3]),
                          "r"(b[na][0]), "r"(b[na][1]));
                }
        }
        __syncthreads();
    }

    #pragma unroll
    for (int ma = 0; ma < 2; ma++) {
        int m0 = bm + wm * 32 + ma * 16 + g;
        #pragma unroll
        for (int na = 0; na < AN; na++) {
            int n = bn + wn * AN * 8 + na * 8 + 2 * tg;
            float bx = 0.f, by = 0.f;
            if (BIAS) { bx = bias[n]; by = bias[n + 1]; }
            float v0 = acc[ma][na][0] + bx, v1 = acc[ma][na][1] + by;
            float v2 = acc[ma][na][2] + bx, v3 = acc[ma][na][3] + by;
            if (RELU) {
                v0 = fmaxf(v0, 0.f); v1 = fmaxf(v1, 0.f);
                v2 = fmaxf(v2, 0.f); v3 = fmaxf(v3, 0.f);
            }
            if constexpr (OUTH) {
                __half* C = (__half*)Cp;
                if (m0 < M)
                    *reinterpret_cast<__half2*>(C + (size_t)m0 * Nc + n) = __floats2half2_rn(v0, v1);
                if (m0 + 8 < M)
                    *reinterpret_cast<__half2*>(C + (size_t)(m0 + 8) * Nc + n) = __floats2half2_rn(v2, v3);
            } else {
                float* C = (float*)Cp;
                if (m0 < M) {
                    float2 o; o.x = v0; o.y = v1;
                    *reinterpret_cast<float2*>(C + (size_t)m0 * Nc + n) = o;
                }
                if (m0 + 8 < M) {
                    float2 o; o.x = v2; o.y = v3;
                    *reinterpret_cast<float2*>(C + (size_t)(m0 + 8) * Nc + n) = o;
                }
            }
        }
    }
}

// ---------------- fused heads: z = agg(h4); mu = zWmu+bmu; ls = zWls+bls ----------------
__global__ __launch_bounds__(256)
void heads_f(const __half* __restrict__ h4,
             const int* __restrict__ rowptr, const int* __restrict__ src,
             const __half* __restrict__ w, const float* __restrict__ dinv,
             const float* __restrict__ Wmu, const float* __restrict__ bmu,
             const float* __restrict__ Wls, const float* __restrict__ bls,
             float* __restrict__ out_mu, float* __restrict__ out_ls, int n) {
    __shared__ float sW[2][32][17];
    __shared__ float sz[8][32];
    int tid = threadIdx.x;
    for (int t = tid; t < 512; t += 256) {
        sW[0][t >> 4][t & 15] = Wmu[t];
        sW[1][t >> 4][t & 15] = Wls[t];
    }
    __syncthreads();

    int wid = tid >> 5, lane = tid & 31;
    int v = blockIdx.x * 8 + wid;
    if (v < n) {
        float dv = dinv[v];
        float acc = dv * __half2float(h4[(size_t)v * 32 + lane]);
        int e0 = rowptr[v], e1 = rowptr[v + 1];
        for (int e = e0; e < e1; e += 4) {
            int4 s4 = *reinterpret_cast<const int4*>(src + e);
            uint2 w4 = *reinterpret_cast<const uint2*>(w + e);
            float2 wlo = __half22float2(u2h2(w4.x));
            float2 whi = __half22float2(u2h2(w4.y));
            float t0 = __half2float(h4[(size_t)s4.x * 32 + lane]);
            float t1 = __half2float(h4[(size_t)s4.y * 32 + lane]);
            float t2 = __half2float(h4[(size_t)s4.z * 32 + lane]);
            float t3 = __half2float(h4[(size_t)s4.w * 32 + lane]);
            acc += wlo.x * t0 + wlo.y * t1 + whi.x * t2 + whi.y * t3;
        }
        sz[wid][lane] = dv * acc;
    }
    __syncwarp();
    if (v < n) {
        int which = lane >> 4;
        int i = lane & 15;
        float a = which ? bls[i] : bmu[i];
        #pragma unroll
        for (int k = 0; k < 32; k++) a += sz[wid][k] * sW[which][k][i];
        float* outp = which ? out_ls : out_mu;
        outp[(size_t)v * 16 + i] = a;
    }
}

// ---------------- host ----------------
static inline void* sym(const void* s) {
    void* p = nullptr;
    cudaGetSymbolAddress(&p, s);
    return p;
}

extern "C" void kernel_launch(void* const* d_in, const int* in_sizes, int n_in,
                              void* d_out, int out_size) {
    const float* x   = (const float*)d_in[0];
    const int*   ei  = (const int*)d_in[1];
    const float* W1  = (const float*)d_in[2];
    const float* b1  = (const float*)d_in[3];
    const float* W2  = (const float*)d_in[4];
    const float* b2  = (const float*)d_in[5];
    const float* W3  = (const float*)d_in[6];
    const float* b3  = (const float*)d_in[7];
    const float* W4  = (const float*)d_in[8];
    const float* b4  = (const float*)d_in[9];
    const float* Wmu = (const float*)d_in[10];
    const float* bmu = (const float*)d_in[11];
    const float* Wls = (const float*)d_in[12];
    const float* bls = (const float*)d_in[13];

    const int N = NN;
    const int E = in_sizes[1] / 2;
    const int* row = ei;
    const int* col = ei + E;

    __half* h0 = (__half*)sym(g_h0);
    __half* h1 = (__half*)sym(g_h1);
    int*   deg  = (int*)sym(g_deg);
    int*   cur  = (int*)sym(g_cursor);
    int*   rp   = (int*)sym(g_rowptr);
    unsigned long long* desc = (unsigned long long*)sym(g_desc);
    int*    srcA = (int*)sym(g_src);
    __half* wA   = (__half*)sym(g_w);
    float* dinv = (float*)sym(g_dinv);

    float* out_mu = (float*)d_out;
    float* out_ls = out_mu + (size_t)N * 16;

    const int NB = (N + 255) / 256;
    const int n4 = N * 128 / 4;

    // ---- CSR build + x->fp16 ----
    cudaMemsetAsync(deg, 0, NN * sizeof(int));
    cudaMemsetAsync(cur, 0, NN * sizeof(int));
    cudaMemsetAsync(desc, 0, 256 * sizeof(unsigned long long));
    histconv_k<<<(n4 + 255) / 256, 256>>>(col, deg, E, x, (__half2*)h0, n4);   // x16 -> h0
    scan_k<<<NB, 256>>>(deg, dinv, rp, desc, srcA, wA, N);
    fill_k<<<(E + 255) / 256, 256>>>(row, col, rp, cur, srcA, wA, dinv, E);

    const int AGG_BLOCKS = (N + 7) / 8;
    const int GY = (N + 127) / 128;

    // L1: agg(x16:h0) -> a1:h1 ; gemm(a1, W1) +b1+relu -> h1g:h0 [N,256]
    agg_h<4, false, false><<<AGG_BLOCKS, 256>>>(h0, h1, rp, srcA, wA, dinv, nullptr, N);
    { dim3 g(2, GY); gemm_h<8, true, true, true><<<g, 256>>>(h1, W1, b1, h0, N, 128, 256); }
    // L2: gemm(h1g, W2) -> t2:h1 [N,128] ; agg +b2+relu -> a2:h0
    { dim3 g(1, GY); gemm_h<8, false, false, true><<<g, 256>>>(h0, W2, nullptr, h1, N, 256, 128); }
    agg_h<4, true, true><<<AGG_BLOCKS, 256>>>(h1, h0, rp, srcA, wA, dinv, b2, N);
    // L3: gemm(a2, W3) -> t3:h1 [N,64] ; agg +b3+relu -> a3:h0
    { dim3 g(1, GY); gemm_h<4, false, false, true><<<g, 256>>>(h0, W3, nullptr, h1, N, 128, 64); }
    agg_h<2, true, true><<<AGG_BLOCKS, 256>>>(h1, h0, rp, srcA, wA, dinv, b3, N);
    // L4: gemm(a3, W4) -> t4:h1 [N,32] ; agg +b4+relu -> h4:h0
    { dim3 g(1, GY); gemm_h<2, false, false, true><<<g, 256>>>(h0, W4, nullptr, h1, N, 64, 32); }
    agg_h<1, true, true><<<AGG_BLOCKS, 256>>>(h1, h0, rp, srcA, wA, dinv, b4, N);
    // fused heads: z = agg(h4:h0), mu/ls GEMM
    heads_f<<<AGG_BLOCKS, 256>>>(h0, rp, srcA, wA, dinv, Wmu, bmu, Wls, bls,
                                 out_mu, out_ls, N);
}

// round 11
// speedup vs baseline: 1.0915x; 1.0764x over previous
#include <cuda_runtime.h>
#include <cuda_fp16.h>
#include <cstddef>
#include <cstdint>

#define NN 50000
#define EE 800000
#define EPAD (EE + 3 * NN + 8)
// packed weight offsets (uint32 half2 elements)
#define O_W1 0
#define O_W2 16384
#define O_W3 32768
#define O_W4 36864
#define TOTPACK 37888

// ---------------- scratch ----------------
__device__ __half g_h0[NN * 256];    // ping
__device__ __half g_h1[NN * 256];    // pong
__device__ int   g_deg[NN];
__device__ int   g_cursor[NN];
__device__ int   g_rowptr[NN + 1];
__device__ unsigned long long g_desc[256];
__device__ int    g_src[EPAD];
__device__ __half g_w[EPAD];
__device__ float g_dinv[NN];
__device__ uint32_t g_wpack[TOTPACK];   // half2 pairs (k even, k odd) per col

__device__ __forceinline__ __half2 u2h2(uint32_t u) {
    return *reinterpret_cast<__half2*>(&u);
}

__device__ __forceinline__ void cp16(uint32_t dst, const void* src) {
    asm volatile("cp.async.ca.shared.global [%0], [%1], 16;\n" :: "r"(dst), "l"(src));
}
#define CP_COMMIT() asm volatile("cp.async.commit_group;\n" ::)
#define CP_WAIT(n)  asm volatile("cp.async.wait_group %0;\n" :: "n"(n))

// ---------------- CSR build + x->fp16 + weight pack (fused) ----------------
__global__ void histconv_k(const int* __restrict__ col, int* deg, int e,
                           const float* __restrict__ x, __half2* __restrict__ x16,
                           int n4, int* cursor, unsigned long long* desc,
                           uint32_t* __restrict__ wpack,
                           const float* __restrict__ W1, const float* __restrict__ W2,
                           const float* __restrict__ W3, const float* __restrict__ W4) {
    int i = blockIdx.x * blockDim.x + threadIdx.x;
    if (i < e) atomicAdd(&deg[col[i]], 1);
    if (i < n4) {
        float4 v = reinterpret_cast<const float4*>(x)[i];
        x16[2 * i]     = __floats2half2_rn(v.x, v.y);
        x16[2 * i + 1] = __floats2half2_rn(v.z, v.w);
    }
    if (i < NN) cursor[i] = 0;
    if (i < 256) desc[i] = 0ull;
    if (i < TOTPACK) {
        int j = i;
        const float* W;
        int Ncols;
        if (j < O_W2) { W = W1; Ncols = 256; }
        else if (j < O_W3) { W = W2; Ncols = 128; j -= O_W2; }
        else if (j < O_W4) { W = W3; Ncols = 64; j -= O_W3; }
        else { W = W4; Ncols = 32; j -= O_W4; }
        int r = j / Ncols, c = j % Ncols;
        __half2 p = __floats2half2_rn(W[(2 * r) * Ncols + c], W[(2 * r + 1) * Ncols + c]);
        wpack[i] = *reinterpret_cast<uint32_t*>(&p);
    }
}

// fused: dinv + scan of padded degree + dummy-slot zeroing
__global__ void scan_k(const int* __restrict__ deg, float* __restrict__ dinv,
                       int* __restrict__ rowptr, unsigned long long* desc,
                       int* __restrict__ src, __half* __restrict__ w, int n) {
    int b = blockIdx.x;
    int i = b * 256 + threadIdx.x;
    int lane = threadIdx.x & 31, wid = threadIdx.x >> 5;

    int d = (i < n) ? deg[i] : 0;
    int pv = (i < n) ? ((d + 3) & ~3) : 0;
    if (i < n) dinv[i] = rsqrtf((float)(d + 1));

    int x = pv;
    #pragma unroll
    for (int off = 1; off < 32; off <<= 1) {
        int t = __shfl_up_sync(0xFFFFFFFFu, x, off);
        if (lane >= off) x += t;
    }
    __shared__ int ws[8];
    __shared__ int s_prefix;
    if (lane == 31) ws[wid] = x;
    __syncthreads();
    if (wid == 0 && lane < 8) {
        int t2 = ws[lane];
        #pragma unroll
        for (int off = 1; off < 8; off <<= 1) {
            int t = __shfl_up_sync(0xFFu, t2, off);
            if (lane >= off) t2 += t;
        }
        ws[lane] = t2;
    }
    __syncthreads();
    int agg = ws[7];

    if (threadIdx.x == 0) {
        if (b == 0) {
            atomicExch(&desc[0], (2ull << 32) | (unsigned)agg);
            s_prefix = 0;
        } else {
            __threadfence();
            atomicExch(&desc[b], (1ull << 32) | (unsigned)agg);
            int prefix = 0;
            int j = b - 1;
            while (true) {
                unsigned long long dj;
                do { dj = atomicAdd(&desc[j], 0ull); } while ((dj >> 32) == 0);
                prefix += (int)(unsigned)dj;
                if ((dj >> 32) == 2) break;
                j--;
            }
            __threadfence();
            atomicExch(&desc[b], (2ull << 32) | (unsigned)(prefix + agg));
            s_prefix = prefix;
        }
    }
    __syncthreads();
    int excl = s_prefix + (wid ? ws[wid - 1] : 0) + (x - pv);
    if (i < n) {
        rowptr[i] = excl;
        if (i == n - 1) rowptr[n] = excl + pv;
        for (int j = d; j < pv; j++) {
            src[excl + j] = 0;
            w[excl + j] = __float2half_rn(0.0f);
        }
    }
}

__global__ void fill_k(const int* __restrict__ row, const int* __restrict__ col,
                       const int* __restrict__ rowptr, int* cursor,
                       int* src, __half* w, const float* __restrict__ dinv, int e) {
    int i = blockIdx.x * blockDim.x + threadIdx.x;
    if (i < e) {
        int r = row[i], c = col[i];
        int p = rowptr[c] + atomicAdd(&cursor[c], 1);
        src[p] = r;
        w[p] = __float2half_rn(dinv[r]);
    }
}

// ---------------- aggregation (fp16 in/out), warp per node ----------------
template <int VEC, bool BIAS, bool RELU>
__global__ void agg_h(const __half* __restrict__ h, __half* __restrict__ out,
                      const int* __restrict__ rowptr, const int* __restrict__ src,
                      const __half* __restrict__ w, const float* __restrict__ dinv,
                      const float* __restrict__ bias, int nNodes) {
    constexpr int F = 32 * VEC;
    int gw = (blockIdx.x * blockDim.x + threadIdx.x) >> 5;
    int lane = threadIdx.x & 31;
    if (gw >= nNodes) return;
    int v = gw;
    int foff = lane * VEC;

    float acc[VEC];
    float dv = dinv[v];

    {
        const __half* hp = h + (size_t)v * F + foff;
        if constexpr (VEC == 4) {
            uint2 r = *reinterpret_cast<const uint2*>(hp);
            float2 f0 = __half22float2(u2h2(r.x));
            float2 f1 = __half22float2(u2h2(r.y));
            acc[0] = dv * f0.x; acc[1] = dv * f0.y; acc[2] = dv * f1.x; acc[3] = dv * f1.y;
        } else if constexpr (VEC == 2) {
            float2 f = __half22float2(*reinterpret_cast<const __half2*>(hp));
            acc[0] = dv * f.x; acc[1] = dv * f.y;
        } else {
            acc[0] = dv * __half2float(*hp);
        }
    }

    int e0 = rowptr[v], e1 = rowptr[v + 1];
    for (int e = e0; e < e1; e += 4) {
        int4 s4 = *reinterpret_cast<const int4*>(src + e);
        uint2 w4 = *reinterpret_cast<const uint2*>(w + e);
        float2 wlo = __half22float2(u2h2(w4.x));
        float2 whi = __half22float2(u2h2(w4.y));

        if constexpr (VEC == 4) {
            uint2 d0 = *reinterpret_cast<const uint2*>(h + (size_t)s4.x * F + foff);
            uint2 d1 = *reinterpret_cast<const uint2*>(h + (size_t)s4.y * F + foff);
            uint2 d2 = *reinterpret_cast<const uint2*>(h + (size_t)s4.z * F + foff);
            uint2 d3 = *reinterpret_cast<const uint2*>(h + (size_t)s4.w * F + foff);
            float2 a0 = __half22float2(u2h2(d0.x)), b0 = __half22float2(u2h2(d0.y));
            float2 a1 = __half22float2(u2h2(d1.x)), b1 = __half22float2(u2h2(d1.y));
            float2 a2 = __half22float2(u2h2(d2.x)), b2 = __half22float2(u2h2(d2.y));
            float2 a3 = __half22float2(u2h2(d3.x)), b3 = __half22float2(u2h2(d3.y));
            acc[0] += wlo.x * a0.x; acc[1] += wlo.x * a0.y; acc[2] += wlo.x * b0.x; acc[3] += wlo.x * b0.y;
            acc[0] += wlo.y * a1.x; acc[1] += wlo.y * a1.y; acc[2] += wlo.y * b1.x; acc[3] += wlo.y * b1.y;
            acc[0] += whi.x * a2.x; acc[1] += whi.x * a2.y; acc[2] += whi.x * b2.x; acc[3] += whi.x * b2.y;
            acc[0] += whi.y * a3.x; acc[1] += whi.y * a3.y; acc[2] += whi.y * b3.x; acc[3] += whi.y * b3.y;
        } else if constexpr (VEC == 2) {
            float2 f0 = __half22float2(*reinterpret_cast<const __half2*>(h + (size_t)s4.x * F + foff));
            float2 f1 = __half22float2(*reinterpret_cast<const __half2*>(h + (size_t)s4.y * F + foff));
            float2 f2 = __half22float2(*reinterpret_cast<const __half2*>(h + (size_t)s4.z * F + foff));
            float2 f3 = __half22float2(*reinterpret_cast<const __half2*>(h + (size_t)s4.w * F + foff));
            acc[0] += wlo.x * f0.x; acc[1] += wlo.x * f0.y;
            acc[0] += wlo.y * f1.x; acc[1] += wlo.y * f1.y;
            acc[0] += whi.x * f2.x; acc[1] += whi.x * f2.y;
            acc[0] += whi.y * f3.x; acc[1] += whi.y * f3.y;
        } else {
            float t0 = __half2float(h[(size_t)s4.x * F + foff]);
            float t1 = __half2float(h[(size_t)s4.y * F + foff]);
            float t2 = __half2float(h[(size_t)s4.z * F + foff]);
            float t3 = __half2float(h[(size_t)s4.w * F + foff]);
            acc[0] += wlo.x * t0 + wlo.y * t1 + whi.x * t2 + whi.y * t3;
        }
    }

    #pragma unroll
    for (int i = 0; i < VEC; i++) {
        float r = dv * acc[i];
        if (BIAS) r += bias[foff + i];
        if (RELU) r = fmaxf(r, 0.0f);
        acc[i] = r;
    }

    __half* op = out + (size_t)v * F + foff;
    if constexpr (VEC == 4) {
        uint2 o;
        *reinterpret_cast<__half2*>(&o.x) = __floats2half2_rn(acc[0], acc[1]);
        *reinterpret_cast<__half2*>(&o.y) = __floats2half2_rn(acc[2], acc[3]);
        *reinterpret_cast<uint2*>(op) = o;
    } else if constexpr (VEC == 2) {
        *reinterpret_cast<__half2*>(op) = __floats2half2_rn(acc[0], acc[1]);
    } else {
        op[0] = __float2half_rn(acc[0]);
    }
}

// ---------------- fp16 tensor-core GEMM: cp.async double-buffered B ----------------
// C[M,Nc] = A[M,K](half) @ W(packed half2 pairs [K/2][Nc]) (+bias)(+relu)
template <int AN, bool BIAS, bool RELU, bool OUTH>
__global__ __launch_bounds__(256, 2)
void gemm_h(const __half* __restrict__ A, const uint32_t* __restrict__ Wp,
            const float* __restrict__ bias, void* __restrict__ Cp,
            int M, int K, int Nc) {
    constexpr int BN = 2 * AN * 8;
    __shared__ uint32_t As[2][4][132][2];              // [kk][c][m][p]
    __shared__ uint32_t Bs[2][2][4][2][BN + 4];        // [buf][kk][c][p][n]

    const int tid = threadIdx.x;
    const int lane = tid & 31, wid = tid >> 5;
    const int g = lane >> 2, tg = lane & 3;
    const int wm = wid & 3, wn = wid >> 2;

    const int bm = blockIdx.y * 128;
    const int bn = blockIdx.x * BN;

    float acc[2][AN][4];
    #pragma unroll
    for (int i = 0; i < 2; i++)
        #pragma unroll
        for (int j = 0; j < AN; j++)
            #pragma unroll
            for (int c = 0; c < 4; c++) acc[i][j][c] = 0.0f;

    const int arow_l = tid >> 1;
    const int kh = (tid & 1) * 16;
    const int akk = kh >> 4;
    const int arow = min(bm + arow_l, M - 1);
    const __half* Abase = A + (size_t)arow * K + kh;

    // B cp.async mapping: 16 packed rows per 32-k tile, BN/4 16B chunks per row.
    // CPR chunks per row; 256 threads cover 256/CPR rows per pass -> NPASS passes.
    constexpr int CPR = BN / 4;
    constexpr int ROWS_PER_PASS = 256 / CPR;
    constexpr int NPASS = (16 + ROWS_PER_PASS - 1) / ROWS_PER_PASS;
    const int brow = tid / CPR;
    const int bc16 = (tid % CPR) * 4;
    uint32_t bdst[2][NPASS];
    bool bact[NPASS];
    #pragma unroll
    for (int p = 0; p < NPASS; p++) {
        int r = brow + p * ROWS_PER_PASS;
        bact[p] = (r < 16);
        if (bact[p]) {
            int kk = r >> 3, cc = r & 3, pp = (r >> 2) & 1;
            bdst[0][p] = (uint32_t)__cvta_generic_to_shared(&Bs[0][kk][cc][pp][bc16]);
            bdst[1][p] = (uint32_t)__cvta_generic_to_shared(&Bs[1][kk][cc][pp][bc16]);
        } else {
            bdst[0][p] = bdst[1][p] = 0;
        }
    }

    const int nt = K / 32;
    // prologue: B tile0 -> buf0 ; A tile0 -> regs
    #pragma unroll
    for (int p = 0; p < NPASS; p++)
        if (bact[p]) cp16(bdst[0][p], Wp + (size_t)(brow + p * ROWS_PER_PASS) * Nc + bn + bc16);
    CP_COMMIT();
    uint4 sa0 = *reinterpret_cast<const uint4*>(Abase);
    uint4 sa1 = *reinterpret_cast<const uint4*>(Abase + 8);

    for (int t = 0; t < nt; t++) {
        const int buf = t & 1;
        // store staged A
        As[akk][0][arow_l][0] = sa0.x;
        As[akk][1][arow_l][0] = sa0.y;
        As[akk][2][arow_l][0] = sa0.z;
        As[akk][3][arow_l][0] = sa0.w;
        As[akk][0][arow_l][1] = sa1.x;
        As[akk][1][arow_l][1] = sa1.y;
        As[akk][2][arow_l][1] = sa1.z;
        As[akk][3][arow_l][1] = sa1.w;

        if (t + 1 < nt) {
            // issue next B tile + stage next A
            #pragma unroll
            for (int p = 0; p < NPASS; p++)
                if (bact[p]) cp16(bdst[buf ^ 1][p],
                                  Wp + (size_t)((t + 1) * 16 + brow + p * ROWS_PER_PASS) * Nc + bn + bc16);
            CP_COMMIT();
            int kt = (t + 1) * 32;
            sa0 = *reinterpret_cast<const uint4*>(Abase + kt);
            sa1 = *reinterpret_cast<const uint4*>(Abase + kt + 8);
            CP_WAIT(1);
        } else {
            CP_WAIT(0);
        }
        __syncthreads();

        #pragma unroll
        for (int kk = 0; kk < 2; kk++) {
            uint32_t a[2][4];
            #pragma unroll
            for (int ma = 0; ma < 2; ma++) {
                int mb = wm * 32 + ma * 16;
                uint2 lo = *reinterpret_cast<const uint2*>(&As[kk][tg][mb + g][0]);
                uint2 hi = *reinterpret_cast<const uint2*>(&As[kk][tg][mb + 8 + g][0]);
                a[ma][0] = lo.x; a[ma][2] = lo.y;
                a[ma][1] = hi.x; a[ma][3] = hi.y;
            }
            uint32_t b[AN][2];
            #pragma unroll
            for (int na = 0; na < AN; na++) {
                int n = wn * AN * 8 + na * 8 + g;
                b[na][0] = Bs[buf][kk][tg][0][n];
                b[na][1] = Bs[buf][kk][tg][1][n];
            }
            #pragma unroll
            for (int ma = 0; ma < 2; ma++)
                #pragma unroll
                for (int na = 0; na < AN; na++) {
                    asm volatile(
                        "mma.sync.aligned.m16n8k16.row.col.f32.f16.f16.f32 "
                        "{%0,%1,%2,%3}, {%4,%5,%6,%7}, {%8,%9}, {%0,%1,%2,%3};\n"
                        : "+f"(acc[ma][na][0]), "+f"(acc[ma][na][1]),
                          "+f"(acc[ma][na][2]), "+f"(acc[ma][na][3])
                        : "r"(a[ma][0]), "r"(a[ma][1]), "r"(a[ma][2]), "r"(a[ma][3]),
                          "r"(b[na][0]), "r"(b[na][1]));
                }
        }
        __syncthreads();
    }

    #pragma unroll
    for (int ma = 0; ma < 2; ma++) {
        int m0 = bm + wm * 32 + ma * 16 + g;
        #pragma unroll
        for (int na = 0; na < AN; na++) {
            int n = bn + wn * AN * 8 + na * 8 + 2 * tg;
            float bx = 0.f, by = 0.f;
            if (BIAS) { bx = bias[n]; by = bias[n + 1]; }
            float v0 = acc[ma][na][0] + bx, v1 = acc[ma][na][1] + by;
            float v2 = acc[ma][na][2] + bx, v3 = acc[ma][na][3] + by;
            if (RELU) {
                v0 = fmaxf(v0, 0.f); v1 = fmaxf(v1, 0.f);
                v2 = fmaxf(v2, 0.f); v3 = fmaxf(v3, 0.f);
            }
            if constexpr (OUTH) {
                __half* C = (__half*)Cp;
                if (m0 < M)
                    *reinterpret_cast<__half2*>(C + (size_t)m0 * Nc + n) = __floats2half2_rn(v0, v1);
                if (m0 + 8 < M)
                    *reinterpret_cast<__half2*>(C + (size_t)(m0 + 8) * Nc + n) = __floats2half2_rn(v2, v3);
            } else {
                float* C = (float*)Cp;
                if (m0 < M) {
                    float2 o; o.x = v0; o.y = v1;
                    *reinterpret_cast<float2*>(C + (size_t)m0 * Nc + n) = o;
                }
                if (m0 + 8 < M) {
                    float2 o; o.x = v2; o.y = v3;
                    *reinterpret_cast<float2*>(C + (size_t)(m0 + 8) * Nc + n) = o;
                }
            }
        }
    }
}

// ---------------- fused heads ----------------
__global__ __launch_bounds__(256)
void heads_f(const __half* __restrict__ h4,
             const int* __restrict__ rowptr, const int* __restrict__ src,
             const __half* __restrict__ w, const float* __restrict__ dinv,
             const float* __restrict__ Wmu, const float* __restrict__ bmu,
             const float* __restrict__ Wls, const float* __restrict__ bls,
             float* __restrict__ out_mu, float* __restrict__ out_ls, int n) {
    __shared__ float sW[2][32][17];
    __shared__ float sz[8][32];
    int tid = threadIdx.x;
    for (int t = tid; t < 512; t += 256) {
        sW[0][t >> 4][t & 15] = Wmu[t];
        sW[1][t >> 4][t & 15] = Wls[t];
    }
    __syncthreads();

    int wid = tid >> 5, lane = tid & 31;
    int v = blockIdx.x * 8 + wid;
    if (v < n) {
        float dv = dinv[v];
        float acc = dv * __half2float(h4[(size_t)v * 32 + lane]);
        int e0 = rowptr[v], e1 = rowptr[v + 1];
        for (int e = e0; e < e1; e += 4) {
            int4 s4 = *reinterpret_cast<const int4*>(src + e);
            uint2 w4 = *reinterpret_cast<const uint2*>(w + e);
            float2 wlo = __half22float2(u2h2(w4.x));
            float2 whi = __half22float2(u2h2(w4.y));
            float t0 = __half2float(h4[(size_t)s4.x * 32 + lane]);
            float t1 = __half2float(h4[(size_t)s4.y * 32 + lane]);
            float t2 = __half2float(h4[(size_t)s4.z * 32 + lane]);
            float t3 = __half2float(h4[(size_t)s4.w * 32 + lane]);
            acc += wlo.x * t0 + wlo.y * t1 + whi.x * t2 + whi.y * t3;
        }
        sz[wid][lane] = dv * acc;
    }
    __syncwarp();
    if (v < n) {
        int which = lane >> 4;
        int i = lane & 15;
        float a = which ? bls[i] : bmu[i];
        #pragma unroll
        for (int k = 0; k < 32; k++) a += sz[wid][k] * sW[which][k][i];
        float* outp = which ? out_ls : out_mu;
        outp[(size_t)v * 16 + i] = a;
    }
}

// ---------------- host ----------------
static inline void* sym(const void* s) {
    void* p = nullptr;
    cudaGetSymbolAddress(&p, s);
    return p;
}

extern "C" void kernel_launch(void* const* d_in, const int* in_sizes, int n_in,
                              void* d_out, int out_size) {
    const float* x   = (const float*)d_in[0];
    const int*   ei  = (const int*)d_in[1];
    const float* W1  = (const float*)d_in[2];
    const float* b1  = (const float*)d_in[3];
    const float* W2  = (const float*)d_in[4];
    const float* b2  = (const float*)d_in[5];
    const float* W3  = (const float*)d_in[6];
    const float* b3  = (const float*)d_in[7];
    const float* W4  = (const float*)d_in[8];
    const float* b4  = (const float*)d_in[9];
    const float* Wmu = (const float*)d_in[10];
    const float* bmu = (const float*)d_in[11];
    const float* Wls = (const float*)d_in[12];
    const float* bls = (const float*)d_in[13];

    const int N = NN;
    const int E = in_sizes[1] / 2;
    const int* row = ei;
    const int* col = ei + E;

    __half* h0 = (__half*)sym(g_h0);
    __half* h1 = (__half*)sym(g_h1);
    int*   deg  = (int*)sym(g_deg);
    int*   cur  = (int*)sym(g_cursor);
    int*   rp   = (int*)sym(g_rowptr);
    unsigned long long* desc = (unsigned long long*)sym(g_desc);
    int*    srcA = (int*)sym(g_src);
    __half* wA   = (__half*)sym(g_w);
    float* dinv = (float*)sym(g_dinv);
    uint32_t* wpack = (uint32_t*)sym(g_wpack);

    float* out_mu = (float*)d_out;
    float* out_ls = out_mu + (size_t)N * 16;

    const int NB = (N + 255) / 256;
    const int n4 = N * 128 / 4;

    // ---- CSR build + x->fp16 + weight pack ----
    cudaMemsetAsync(deg, 0, NN * sizeof(int));
    histconv_k<<<(n4 + 255) / 256, 256>>>(col, deg, E, x, (__half2*)h0, n4,
                                          cur, desc, wpack, W1, W2, W3, W4);
    scan_k<<<NB, 256>>>(deg, dinv, rp, desc, srcA, wA, N);
    fill_k<<<(E + 255) / 256, 256>>>(row, col, rp, cur, srcA, wA, dinv, E);

    const int AGG_BLOCKS = (N + 7) / 8;
    const int GY = (N + 127) / 128;

    // L1: agg(x16:h0) -> a1:h1 ; gemm(a1, W1) +b1+relu -> h0 [N,256]
    agg_h<4, false, false><<<AGG_BLOCKS, 256>>>(h0, h1, rp, srcA, wA, dinv, nullptr, N);
    { dim3 g(2, GY); gemm_h<8, true, true, true><<<g, 256>>>(h1, wpack + O_W1, b1, h0, N, 128, 256); }
    // L2: gemm -> t2:h1 [N,128] ; agg +b2+relu -> h0
    { dim3 g(1, GY); gemm_h<8, false, false, true><<<g, 256>>>(h0, wpack + O_W2, nullptr, h1, N, 256, 128); }
    agg_h<4, true, true><<<AGG_BLOCKS, 256>>>(h1, h0, rp, srcA, wA, dinv, b2, N);
    // L3: gemm -> t3:h1 [N,64] ; agg +b3+relu -> h0
    { dim3 g(1, GY); gemm_h<4, false, false, true><<<g, 256>>>(h0, wpack + O_W3, nullptr, h1, N, 128, 64); }
    agg_h<2, true, true><<<AGG_BLOCKS, 256>>>(h1, h0, rp, srcA, wA, dinv, b3, N);
    // L4: gemm -> t4:h1 [N,32] ; agg +b4+relu -> h4:h0
    { dim3 g(1, GY); gemm_h<2, false, false, true><<<g, 256>>>(h0, wpack + O_W4, nullptr, h1, N, 64, 32); }
    agg_h<1, true, true><<<AGG_BLOCKS, 256>>>(h1, h0, rp, srcA, wA, dinv, b4, N);
    // fused heads
    heads_f<<<AGG_BLOCKS, 256>>>(h0, rp, srcA, wA, dinv, Wmu, bmu, Wls, bls,
                                 out_mu, out_ls, N);
}